// round 5
// baseline (speedup 1.0000x reference)
#include <cuda_runtime.h>
#include <math.h>

// Problem constants
#define NB    32
#define NFEAT 64
#define NH    256
#define NP    96
#define TILE  32      // rows per CTA
#define NT    256
#define HS    36      // smem row stride in floats (144B: 16B-aligned, 4-way max conflicts)

#define TWO_PI_F   6.2831853071795864769f
#define MIN_WH     1e-3f
#define MIN_D      1e-3f
#define DERIV_OFF  0.5413248546129181f   // log(e-1)
#define SIZE_SCALE (1.0f - 1e-3f * 32.0f)

__device__ __forceinline__ float softplus_f(float x) {
    return (x > 0.0f) ? (x + log1pf(expf(-x))) : log1pf(expf(x));
}

// ---- packed f32x2 helpers (sm_103a) ----
__device__ __forceinline__ unsigned long long pack2(float v) {
    unsigned long long r;
    asm("mov.b64 %0, {%1, %1};" : "=l"(r) : "f"(v));
    return r;
}
__device__ __forceinline__ void ffma2(unsigned long long &d,
                                      unsigned long long a,
                                      unsigned long long b) {
    asm("fma.rn.f32x2 %0, %1, %2, %0;" : "+l"(d) : "l"(a), "l"(b));
}
__device__ __forceinline__ float2 unpack2(unsigned long long v) {
    float2 f;
    asm("mov.b64 {%0, %1}, %2;" : "=f"(f.x), "=f"(f.y) : "l"(v));
    return f;
}

__global__ __launch_bounds__(NT)
void cyl_flow_kernel(const float* __restrict__ theta,
                     const float* __restrict__ xc,
                     const float* __restrict__ W1,
                     const float* __restrict__ b1,
                     const float* __restrict__ W2,
                     const float* __restrict__ b2,
                     const float* __restrict__ eta,
                     float* __restrict__ out,
                     int B)
{
    // h_t[k][r]: transposed hidden, stride HS floats          -> 36864 B
    // buf: union of x_t (64*HS = 9216 B) and pp[32][96] (12288 B)
    // total static smem = 49152 B (48 KB) -> up to 4 CTAs/SM
    __shared__ __align__(16) float h_t[NH * HS];
    __shared__ __align__(16) float buf[TILE * NP];

    float* const x_t = buf;   // stage-1 input tile (transposed)
    float* const pp  = buf;   // stage-2 partials / final spline params

    const int t    = threadIdx.x;
    const int row0 = blockIdx.x * TILE;

    // ---- load x tile, transposed (coalesced LDG; 4-way STS conflicts, one-time) ----
    #pragma unroll
    for (int i = t; i < TILE * NFEAT; i += NT) {
        int r = i >> 6, k = i & 63;
        int row = row0 + r;
        x_t[k * HS + r] = (row < B) ? xc[row * NFEAT + k] : 0.0f;
    }
    __syncthreads();

    // ---- stage 1: h = relu(x @ W1 + b1) ----
    // thread = 2 columns (2cg, 2cg+1) x 16 rows (rg*16..+15)
    {
        const int cg = t & 127;
        const int rg = t >> 7;
        unsigned long long acc[16];
        #pragma unroll
        for (int j = 0; j < 16; j++) acc[j] = 0ULL;

        const float2* w1p = (const float2*)W1 + cg;
        #pragma unroll 4
        for (int k = 0; k < NFEAT; k++) {
            float2 w = w1p[k * (NH / 2)];                     // LDG.64, coalesced
            unsigned long long wx = pack2(w.x), wy = pack2(w.y);
            const ulonglong2* xp = (const ulonglong2*)(x_t + k * HS + rg * 16);
            ulonglong2 a0 = xp[0], a1 = xp[1], a2 = xp[2], a3 = xp[3];  // LDS.128 broadcast
            ffma2(acc[0], a0.x, wx);  ffma2(acc[1], a0.y, wx);
            ffma2(acc[2], a1.x, wx);  ffma2(acc[3], a1.y, wx);
            ffma2(acc[4], a2.x, wx);  ffma2(acc[5], a2.y, wx);
            ffma2(acc[6], a3.x, wx);  ffma2(acc[7], a3.y, wx);
            ffma2(acc[8],  a0.x, wy); ffma2(acc[9],  a0.y, wy);
            ffma2(acc[10], a1.x, wy); ffma2(acc[11], a1.y, wy);
            ffma2(acc[12], a2.x, wy); ffma2(acc[13], a2.y, wy);
            ffma2(acc[14], a3.x, wy); ffma2(acc[15], a3.y, wy);
        }
        float bb0 = b1[2 * cg];
        float bb1 = b1[2 * cg + 1];
        #pragma unroll
        for (int cc = 0; cc < 2; cc++) {
            float bb = cc ? bb1 : bb0;
            float* hp = h_t + (2 * cg + cc) * HS + rg * 16;
            #pragma unroll
            for (int q = 0; q < 4; q++) {
                float2 f0 = unpack2(acc[cc * 8 + 2 * q]);
                float2 f1 = unpack2(acc[cc * 8 + 2 * q + 1]);
                float4 hv;
                hv.x = fmaxf(f0.x + bb, 0.0f);
                hv.y = fmaxf(f0.y + bb, 0.0f);
                hv.z = fmaxf(f1.x + bb, 0.0f);
                hv.w = fmaxf(f1.y + bb, 0.0f);
                *(float4*)(hp + 4 * q) = hv;                  // STS.128, 4-way max
            }
        }
    }
    __syncthreads();

    // ---- stage 2: params = (h @ W2 + b2) * eta ----
    // 128 active threads: thread = 3 cols (cg, cg+32, cg+64) x 16 rows, k-half g
    unsigned long long acc2[24];
    const int cg2 = t & 31;
    const int rg2 = (t >> 5) & 1;
    const int g2  = t >> 6;         // 0 or 1 for t<128

    if (t < 128) {
        #pragma unroll
        for (int j = 0; j < 24; j++) acc2[j] = 0ULL;
        const int k0 = g2 * (NH / 2);
        #pragma unroll 2
        for (int kk = 0; kk < NH / 2; kk++) {
            int k = k0 + kk;
            const float* w2p = W2 + k * NP + cg2;
            unsigned long long w0 = pack2(w2p[0]);            // 3x LDG.32, each coalesced 128B
            unsigned long long w1 = pack2(w2p[32]);
            unsigned long long w2v = pack2(w2p[64]);
            const ulonglong2* hp = (const ulonglong2*)(h_t + k * HS + rg2 * 16);
            ulonglong2 a0 = hp[0], a1 = hp[1], a2 = hp[2], a3 = hp[3];
            ffma2(acc2[0], a0.x, w0);  ffma2(acc2[1], a0.y, w0);
            ffma2(acc2[2], a1.x, w0);  ffma2(acc2[3], a1.y, w0);
            ffma2(acc2[4], a2.x, w0);  ffma2(acc2[5], a2.y, w0);
            ffma2(acc2[6], a3.x, w0);  ffma2(acc2[7], a3.y, w0);
            ffma2(acc2[8],  a0.x, w1); ffma2(acc2[9],  a0.y, w1);
            ffma2(acc2[10], a1.x, w1); ffma2(acc2[11], a1.y, w1);
            ffma2(acc2[12], a2.x, w1); ffma2(acc2[13], a2.y, w1);
            ffma2(acc2[14], a3.x, w1); ffma2(acc2[15], a3.y, w1);
            ffma2(acc2[16], a0.x, w2v); ffma2(acc2[17], a0.y, w2v);
            ffma2(acc2[18], a1.x, w2v); ffma2(acc2[19], a1.y, w2v);
            ffma2(acc2[20], a2.x, w2v); ffma2(acc2[21], a2.y, w2v);
            ffma2(acc2[22], a3.x, w2v); ffma2(acc2[23], a3.y, w2v);
        }
        if (g2 == 1) {
            // write k-upper-half partials
            #pragma unroll
            for (int cc = 0; cc < 3; cc++) {
                int col = cg2 + cc * 32;
                #pragma unroll
                for (int j = 0; j < 8; j++) {
                    float2 f = unpack2(acc2[cc * 8 + j]);
                    pp[(rg2 * 16 + 2 * j)     * NP + col] = f.x;   // conflict-free (consec cols)
                    pp[(rg2 * 16 + 2 * j + 1) * NP + col] = f.y;
                }
            }
        }
    }
    __syncthreads();

    if (t < 64) {   // g2 == 0: combine halves, finalize params in place
        float e0 = eta[0];
        #pragma unroll
        for (int cc = 0; cc < 3; cc++) {
            int col = cg2 + cc * 32;
            float bb = b2[col];
            #pragma unroll
            for (int j = 0; j < 8; j++) {
                float2 f = unpack2(acc2[cc * 8 + j]);
                int r0i = rg2 * 16 + 2 * j;
                float v0 = (f.x + pp[r0i * NP + col] + bb) * e0;
                float v1 = (f.y + pp[(r0i + 1) * NP + col] + bb) * e0;
                pp[r0i * NP + col]       = v0;
                pp[(r0i + 1) * NP + col] = v1;
            }
        }
    }
    __syncthreads();

    // ---- stage 3: circular RQ spline, warp per row, lane = bin ----
    const int wid  = t >> 5;
    const int lane = t & 31;
    const unsigned FULL = 0xffffffffu;

    for (int rr = wid; rr < TILE; rr += NT / 32) {
        int row = row0 + rr;
        if (row >= B) continue;                 // warp-uniform

        float th_in = theta[row];
        float uw = pp[rr * NP + lane];
        float uh = pp[rr * NP + NB + lane];
        float ud = pp[rr * NP + 2 * NB + lane] + DERIV_OFF;

        // softmax (max-subtracted, matching jax.nn.softmax)
        float mw = uw, mh = uh;
        #pragma unroll
        for (int o = 16; o; o >>= 1) {
            mw = fmaxf(mw, __shfl_xor_sync(FULL, mw, o));
            mh = fmaxf(mh, __shfl_xor_sync(FULL, mh, o));
        }
        float ew = expf(uw - mw), eh = expf(uh - mh);
        float sw = ew, sh = eh;
        #pragma unroll
        for (int o = 16; o; o >>= 1) {
            sw += __shfl_xor_sync(FULL, sw, o);
            sh += __shfl_xor_sync(FULL, sh, o);
        }
        float szw = MIN_WH + SIZE_SCALE * (ew / sw);
        float szh = MIN_WH + SIZE_SCALE * (eh / sh);

        // inclusive scan -> cumulative sizes
        float cw = szw, chs = szh;
        #pragma unroll
        for (int o = 1; o < 32; o <<= 1) {
            float a = __shfl_up_sync(FULL, cw,  o);
            float b = __shfl_up_sync(FULL, chs, o);
            if (lane >= o) { cw += a; chs += b; }
        }

        // knots: lane j holds knot (j+1); knot 32 forced to 2*pi, knot 0 = 0
        float kw = (lane == 31) ? TWO_PI_F : TWO_PI_F * cw;
        float kh = (lane == 31) ? TWO_PI_F : TWO_PI_F * chs;

        unsigned bal = __ballot_sync(FULL, th_in >= kw);
        int bin = __popc(bal);
        if (bin > NB - 1) bin = NB - 1;
        int lo = (bin > 0) ? bin - 1 : 0;

        float cw_hi = __shfl_sync(FULL, kw, bin);
        float cw_lo = __shfl_sync(FULL, kw, lo);
        float ch_hi = __shfl_sync(FULL, kh, bin);
        float ch_lo = __shfl_sync(FULL, kh, lo);
        if (bin == 0) { cw_lo = 0.0f; ch_lo = 0.0f; }

        float in_w = cw_hi - cw_lo;
        float in_h = ch_hi - ch_lo;

        float dsp  = MIN_D + softplus_f(ud);
        float d_k  = __shfl_sync(FULL, dsp, bin);
        float d_k1 = __shfl_sync(FULL, dsp, (bin + 1) & 31);

        float delta = in_h / in_w;
        float th    = (th_in - cw_lo) / in_w;
        float om    = th * (1.0f - th);
        float den   = delta + (d_k1 + d_k - 2.0f * delta) * om;
        float num   = in_h * (delta * th * th + d_k * om);
        float outv  = ch_lo + num / den;

        float omt = 1.0f - th;
        float dn  = delta * delta * (d_k1 * th * th + 2.0f * delta * om + d_k * omt * omt);
        float lad = logf(dn) - 2.0f * logf(den);

        if (lane == 0) {
            out[row]     = outv;
            out[B + row] = lad;
        }
    }
}

extern "C" void kernel_launch(void* const* d_in, const int* in_sizes, int n_in,
                              void* d_out, int out_size)
{
    const float* theta = (const float*)d_in[0];
    const float* xc    = (const float*)d_in[1];
    const float* W1    = (const float*)d_in[2];
    const float* b1    = (const float*)d_in[3];
    const float* W2    = (const float*)d_in[4];
    const float* b2    = (const float*)d_in[5];
    const float* eta   = (const float*)d_in[6];
    float* out = (float*)d_out;

    int B = in_sizes[0];
    int grid = (B + TILE - 1) / TILE;
    cyl_flow_kernel<<<grid, NT>>>(theta, xc, W1, b1, W2, b2, eta, out, B);
}

// round 7
// speedup vs baseline: 1.8315x; 1.8315x over previous
#include <cuda_runtime.h>
#include <cuda_bf16.h>
#include <math.h>
#include <stdint.h>

// ---------------- problem constants ----------------
#define NB     32
#define NFEAT  64
#define NH     256
#define NP     96
#define MROWS  64           // rows per CTA
#define NT     256

#define TWO_PI_F   6.2831853071795864769f
#define MIN_WH     1e-3f
#define MIN_D      1e-3f
#define DERIV_OFF  0.5413248546129181f     // log(e-1)
#define SIZE_SCALE (1.0f - 1e-3f * 32.0f)

// ---- padded smem row strides (bytes): odd multiple of 16B -> conflict-free ldmatrix
#define S64   144     // rows of 64 bf16 padded to 72  (9 x 16B)
#define S256  528     // rows of 256 bf16 padded to 264 (33 x 16B)

// ---- smem layout (bytes) ----
// phase 1: XH 0 (9216) | XL 9216 | W1H 18432 (36864) | W1L 55296  -> end 92160
// phase 2 (reuse):  hH 0 (33792) | hL 33792           -> end 67584
// phase 3 (reuse):  pp 0 (24576 f32 params)
// persistent:       W2H 92160 (50688) | W2L 142848    -> total 193536
#define SM_XH   0
#define SM_XL   9216
#define SM_W1H  18432
#define SM_W1L  55296
#define SM_HH   0
#define SM_HL   33792
#define SM_PP   0
#define SM_W2H  92160
#define SM_W2L  142848
#define SM_TOTAL 193536

// ---------------- pre-split weights (device globals) ----------------
__device__ uint32_t g_W1T_hi[NH * NFEAT / 2];   // [n][k] bf16 pairs
__device__ uint32_t g_W1T_lo[NH * NFEAT / 2];
__device__ uint32_t g_W2T_hi[NP * NH / 2];      // [n][k]
__device__ uint32_t g_W2T_lo[NP * NH / 2];

// ---------------- helpers ----------------
static __device__ __forceinline__ uint32_t smem_u32(const void* p) {
    uint32_t a;
    asm("{ .reg .u64 t; cvta.to.shared.u64 t, %1; cvt.u32.u64 %0, t; }" : "=r"(a) : "l"(p));
    return a;
}
static __device__ __forceinline__ void ldsm_x4(uint32_t addr, uint32_t r[4]) {
    asm volatile("ldmatrix.sync.aligned.m8n8.x4.shared.b16 {%0,%1,%2,%3}, [%4];"
                 : "=r"(r[0]), "=r"(r[1]), "=r"(r[2]), "=r"(r[3]) : "r"(addr));
}
static __device__ __forceinline__ void ldsm_x2(uint32_t addr, uint32_t r[2]) {
    asm volatile("ldmatrix.sync.aligned.m8n8.x2.shared.b16 {%0,%1}, [%2];"
                 : "=r"(r[0]), "=r"(r[1]) : "r"(addr));
}
static __device__ __forceinline__ void mma16816(float c[4], const uint32_t a[4], const uint32_t b[2]) {
    asm volatile("mma.sync.aligned.m16n8k16.row.col.f32.bf16.bf16.f32 "
                 "{%0,%1,%2,%3}, {%4,%5,%6,%7}, {%8,%9}, {%0,%1,%2,%3};"
                 : "+f"(c[0]), "+f"(c[1]), "+f"(c[2]), "+f"(c[3])
                 : "r"(a[0]), "r"(a[1]), "r"(a[2]), "r"(a[3]), "r"(b[0]), "r"(b[1]));
}
static __device__ __forceinline__ uint32_t pack_hi(float v0, float v1) {
    __nv_bfloat16 h0 = __float2bfloat16_rn(v0), h1 = __float2bfloat16_rn(v1);
    return (uint32_t)__bfloat16_as_ushort(h0) | ((uint32_t)__bfloat16_as_ushort(h1) << 16);
}
static __device__ __forceinline__ uint32_t pack_lo(float v0, float v1) {
    __nv_bfloat16 h0 = __float2bfloat16_rn(v0), h1 = __float2bfloat16_rn(v1);
    __nv_bfloat16 l0 = __float2bfloat16_rn(v0 - __bfloat162float(h0));
    __nv_bfloat16 l1 = __float2bfloat16_rn(v1 - __bfloat162float(h1));
    return (uint32_t)__bfloat16_as_ushort(l0) | ((uint32_t)__bfloat16_as_ushort(l1) << 16);
}
static __device__ __forceinline__ float softplus_f(float x) {
    return (x > 0.0f) ? (x + log1pf(expf(-x))) : log1pf(expf(x));
}

// ---------------- prep: split W1^T, W2^T into bf16 hi/lo [n][k] pairs ----------------
__global__ void prep_kernel(const float* __restrict__ W1, const float* __restrict__ W2)
{
    int i = blockIdx.x * blockDim.x + threadIdx.x;
    if (i < NH * NFEAT / 2) {                 // W1 [64][256] -> W1T[n][k]
        int n = i >> 5, kp = i & 31;
        float w0 = W1[(2 * kp)     * NH + n];
        float w1 = W1[(2 * kp + 1) * NH + n];
        g_W1T_hi[i] = pack_hi(w0, w1);
        g_W1T_lo[i] = pack_lo(w0, w1);
    }
    int j = i - NH * NFEAT / 2;
    if (j >= 0 && j < NP * NH / 2) {          // W2 [256][96] -> W2T[n][k]
        int n = j >> 7, kp = j & 127;
        float w0 = W2[(2 * kp)     * NP + n];
        float w1 = W2[(2 * kp + 1) * NP + n];
        g_W2T_hi[j] = pack_hi(w0, w1);
        g_W2T_lo[j] = pack_lo(w0, w1);
    }
}

// ---------------- main fused kernel ----------------
__global__ __launch_bounds__(NT, 1)
void cyl_mma_kernel(const float* __restrict__ theta,
                    const float* __restrict__ xc,
                    const float* __restrict__ b1,
                    const float* __restrict__ b2,
                    const float* __restrict__ eta,
                    float* __restrict__ out,
                    int B)
{
    extern __shared__ char smem[];
    const uint32_t smb = smem_u32(smem);
    const int t    = threadIdx.x;
    const int w    = t >> 5;
    const int l    = t & 31;
    const int row0 = blockIdx.x * MROWS;

    // ---- phase 0: stage inputs into smem ----
    {   // X [64 rows][64 k] f32 -> bf16 hi/lo, padded rows S64
        const float2* xp = (const float2*)xc;
        #pragma unroll
        for (int it = 0; it < (MROWS * 32) / NT; it++) {
            int i = t + it * NT;
            int r = i >> 5, kp = i & 31;
            int row = row0 + r;
            float2 v = (row < B) ? xp[row * 32 + kp] : make_float2(0.f, 0.f);
            *(uint32_t*)(smem + SM_XH + r * S64 + kp * 4) = pack_hi(v.x, v.y);
            *(uint32_t*)(smem + SM_XL + r * S64 + kp * 4) = pack_lo(v.x, v.y);
        }
        #pragma unroll
        for (int it = 0; it < (NH * 32) / NT; it++) {   // W1T [256 n][64 k]
            int i = t + it * NT;
            int n = i >> 5, kp = i & 31;
            *(uint32_t*)(smem + SM_W1H + n * S64 + kp * 4) = g_W1T_hi[i];
            *(uint32_t*)(smem + SM_W1L + n * S64 + kp * 4) = g_W1T_lo[i];
        }
        #pragma unroll
        for (int it = 0; it < (NP * 128) / NT; it++) {  // W2T [96 n][256 k]
            int i = t + it * NT;
            int n = i >> 7, kp = i & 127;
            *(uint32_t*)(smem + SM_W2H + n * S256 + kp * 4) = g_W2T_hi[i];
            *(uint32_t*)(smem + SM_W2L + n * S256 + kp * 4) = g_W2T_lo[i];
        }
    }
    __syncthreads();

    // ldmatrix lane-address components
    const uint32_t aoff64  = (uint32_t)((l & 15) * S64  + ((l >> 4) & 1) * 16);
    const uint32_t boff64  = (uint32_t)((l & 7)  * S64  + ((l >> 3) & 1) * 16);
    const uint32_t aoff256 = (uint32_t)((l & 15) * S256 + ((l >> 4) & 1) * 16);
    const uint32_t boff256 = (uint32_t)((l & 7)  * S256 + ((l >> 3) & 1) * 16);

    // ---- stage 1: C1[64 x 32-slice] = X @ W1 (3-term bf16) ----
    // warp w owns n-cols [32w, 32w+32): 4 n-tiles x 4 m-tiles
    float C1[4][4][4];
    #pragma unroll
    for (int m = 0; m < 4; m++)
        #pragma unroll
        for (int n = 0; n < 4; n++)
            #pragma unroll
            for (int q = 0; q < 4; q++) C1[m][n][q] = 0.f;

    #pragma unroll
    for (int k = 0; k < 4; k++) {
        uint32_t Ah[4][4], Al[4][4];
        #pragma unroll
        for (int m = 0; m < 4; m++) {
            ldsm_x4(smb + SM_XH + aoff64 + (uint32_t)(m * 16 * S64 + k * 32), Ah[m]);
            ldsm_x4(smb + SM_XL + aoff64 + (uint32_t)(m * 16 * S64 + k * 32), Al[m]);
        }
        #pragma unroll
        for (int n = 0; n < 4; n++) {
            uint32_t Bh[2], Bl[2];
            uint32_t nb = (uint32_t)((w * 32 + n * 8) * S64 + k * 32);
            ldsm_x2(smb + SM_W1H + boff64 + nb, Bh);
            ldsm_x2(smb + SM_W1L + boff64 + nb, Bl);
            #pragma unroll
            for (int m = 0; m < 4; m++) {
                mma16816(C1[m][n], Ah[m], Bh);
                mma16816(C1[m][n], Ah[m], Bl);
                mma16816(C1[m][n], Al[m], Bh);
            }
        }
    }
    __syncthreads();   // all warps done reading X/W1 before h overwrites region

    // ---- epilogue 1: h = relu(C1 + b1) -> bf16 hi/lo in smem ----
    {
        const int rq = l >> 2;
        const int cq = 2 * (l & 3);
        #pragma unroll
        for (int n = 0; n < 4; n++) {
            int col = w * 32 + n * 8 + cq;
            float bb0 = b1[col], bb1 = b1[col + 1];
            #pragma unroll
            for (int m = 0; m < 4; m++) {
                int r0i = m * 16 + rq;
                float v0 = fmaxf(C1[m][n][0] + bb0, 0.f);
                float v1 = fmaxf(C1[m][n][1] + bb1, 0.f);
                float v2 = fmaxf(C1[m][n][2] + bb0, 0.f);
                float v3 = fmaxf(C1[m][n][3] + bb1, 0.f);
                uint32_t o0 = (uint32_t)(r0i * S256 + col * 2);
                uint32_t o1 = (uint32_t)((r0i + 8) * S256 + col * 2);
                *(uint32_t*)(smem + SM_HH + o0) = pack_hi(v0, v1);
                *(uint32_t*)(smem + SM_HL + o0) = pack_lo(v0, v1);
                *(uint32_t*)(smem + SM_HH + o1) = pack_hi(v2, v3);
                *(uint32_t*)(smem + SM_HL + o1) = pack_lo(v2, v3);
            }
        }
    }
    __syncthreads();

    // ---- stage 2: C2 = h @ W2 (3-term bf16) ----
    // warp w: m-group mg = w>>2 (rows mg*32..+31), n-group ng = w&3 (cols ng*24..+23)
    const int mg = w >> 2, ng = w & 3;
    float C2[2][3][4];
    #pragma unroll
    for (int m = 0; m < 2; m++)
        #pragma unroll
        for (int n = 0; n < 3; n++)
            #pragma unroll
            for (int q = 0; q < 4; q++) C2[m][n][q] = 0.f;

    #pragma unroll 4
    for (int k = 0; k < 16; k++) {
        uint32_t Ah[2][4], Al[2][4];
        #pragma unroll
        for (int m = 0; m < 2; m++) {
            uint32_t ro = (uint32_t)((mg * 32 + m * 16) * S256 + k * 32);
            ldsm_x4(smb + SM_HH + aoff256 + ro, Ah[m]);
            ldsm_x4(smb + SM_HL + aoff256 + ro, Al[m]);
        }
        #pragma unroll
        for (int n = 0; n < 3; n++) {
            uint32_t Bh[2], Bl[2];
            uint32_t nb = (uint32_t)((ng * 24 + n * 8) * S256 + k * 32);
            ldsm_x2(smb + SM_W2H + boff256 + nb, Bh);
            ldsm_x2(smb + SM_W2L + boff256 + nb, Bl);
            #pragma unroll
            for (int m = 0; m < 2; m++) {
                mma16816(C2[m][n], Ah[m], Bh);
                mma16816(C2[m][n], Ah[m], Bl);
                mma16816(C2[m][n], Al[m], Bh);
            }
        }
    }
    __syncthreads();   // h reads complete before pp overwrites region

    // ---- epilogue 2: pp = (C2 + b2) * eta ----
    {
        float* pp = (float*)(smem + SM_PP);
        float e0 = eta[0];
        const int rq = l >> 2;
        const int cq = 2 * (l & 3);
        #pragma unroll
        for (int n = 0; n < 3; n++) {
            int col = ng * 24 + n * 8 + cq;
            float bb0 = b2[col], bb1 = b2[col + 1];
            #pragma unroll
            for (int m = 0; m < 2; m++) {
                int r0i = mg * 32 + m * 16 + rq;
                pp[r0i * NP + col]           = (C2[m][n][0] + bb0) * e0;
                pp[r0i * NP + col + 1]       = (C2[m][n][1] + bb1) * e0;
                pp[(r0i + 8) * NP + col]     = (C2[m][n][2] + bb0) * e0;
                pp[(r0i + 8) * NP + col + 1] = (C2[m][n][3] + bb1) * e0;
            }
        }
    }
    __syncthreads();

    // ---- stage 3: circular RQ spline, warp per row, lane = bin (proven R4 path) ----
    {
        const float* pp = (const float*)(smem + SM_PP);
        const unsigned FULL = 0xffffffffu;

        for (int rr = w; rr < MROWS; rr += NT / 32) {
            int row = row0 + rr;
            if (row >= B) continue;

            float th_in = theta[row];
            float uw = pp[rr * NP + l];
            float uh = pp[rr * NP + NB + l];
            float ud = pp[rr * NP + 2 * NB + l] + DERIV_OFF;

            float mw = uw, mh = uh;
            #pragma unroll
            for (int o = 16; o; o >>= 1) {
                mw = fmaxf(mw, __shfl_xor_sync(FULL, mw, o));
                mh = fmaxf(mh, __shfl_xor_sync(FULL, mh, o));
            }
            float ew = expf(uw - mw), eh = expf(uh - mh);
            float sw = ew, sh = eh;
            #pragma unroll
            for (int o = 16; o; o >>= 1) {
                sw += __shfl_xor_sync(FULL, sw, o);
                sh += __shfl_xor_sync(FULL, sh, o);
            }
            float szw = MIN_WH + SIZE_SCALE * (ew / sw);
            float szh = MIN_WH + SIZE_SCALE * (eh / sh);

            float cw = szw, chs = szh;
            #pragma unroll
            for (int o = 1; o < 32; o <<= 1) {
                float a = __shfl_up_sync(FULL, cw,  o);
                float b = __shfl_up_sync(FULL, chs, o);
                if (l >= o) { cw += a; chs += b; }
            }

            float kw = (l == 31) ? TWO_PI_F : TWO_PI_F * cw;
            float kh = (l == 31) ? TWO_PI_F : TWO_PI_F * chs;

            unsigned bal = __ballot_sync(FULL, th_in >= kw);
            int bin = __popc(bal);
            if (bin > NB - 1) bin = NB - 1;
            int lo = (bin > 0) ? bin - 1 : 0;

            float cw_hi = __shfl_sync(FULL, kw, bin);
            float cw_lo = __shfl_sync(FULL, kw, lo);
            float ch_hi = __shfl_sync(FULL, kh, bin);
            float ch_lo = __shfl_sync(FULL, kh, lo);
            if (bin == 0) { cw_lo = 0.0f; ch_lo = 0.0f; }

            float in_w = cw_hi - cw_lo;
            float in_h = ch_hi - ch_lo;

            float dsp  = MIN_D + softplus_f(ud);
            float d_k  = __shfl_sync(FULL, dsp, bin);
            float d_k1 = __shfl_sync(FULL, dsp, (bin + 1) & 31);

            float delta = in_h / in_w;
            float th    = (th_in - cw_lo) / in_w;
            float om    = th * (1.0f - th);
            float den   = delta + (d_k1 + d_k - 2.0f * delta) * om;
            float num   = in_h * (delta * th * th + d_k * om);
            float outv  = ch_lo + num / den;

            float omt = 1.0f - th;
            float dn  = delta * delta * (d_k1 * th * th + 2.0f * delta * om + d_k * omt * omt);
            float lad = logf(dn) - 2.0f * logf(den);

            if (l == 0) {
                out[row]     = outv;
                out[B + row] = lad;
            }
        }
    }
}

extern "C" void kernel_launch(void* const* d_in, const int* in_sizes, int n_in,
                              void* d_out, int out_size)
{
    const float* theta = (const float*)d_in[0];
    const float* xc    = (const float*)d_in[1];
    const float* W1    = (const float*)d_in[2];
    const float* b1    = (const float*)d_in[3];
    const float* W2    = (const float*)d_in[4];
    const float* b2    = (const float*)d_in[5];
    const float* eta   = (const float*)d_in[6];
    float* out = (float*)d_out;

    int B = in_sizes[0];

    static bool attr_set = false;
    if (!attr_set) {
        cudaFuncSetAttribute(cyl_mma_kernel, cudaFuncAttributeMaxDynamicSharedMemorySize, SM_TOTAL);
        attr_set = true;
    }

    int prep_elems = NH * NFEAT / 2 + NP * NH / 2;
    prep_kernel<<<(prep_elems + 255) / 256, 256>>>(W1, W2);

    int grid = (B + MROWS - 1) / MROWS;
    cyl_mma_kernel<<<grid, NT, SM_TOTAL>>>(theta, xc, b1, b2, eta, out, B);
}

// round 8
// speedup vs baseline: 1.9610x; 1.0707x over previous
#include <cuda_runtime.h>
#include <cuda_bf16.h>
#include <math.h>
#include <stdint.h>

// ---------------- problem constants ----------------
#define NB     32
#define NFEAT  64
#define NH     256
#define NP     96
#define TM     32           // rows per tile
#define NT     256

#define TWO_PI_F   6.2831853071795864769f
#define MIN_WH     1e-3f
#define MIN_D      1e-3f
#define DERIV_OFF  0.5413248546129181f     // log(e-1)
#define SIZE_SCALE (1.0f - 1e-3f * 32.0f)

// ---- smem layout (bytes), all regions resident for whole kernel ----
#define SM_W1H   0          // W1T hi [256 n][64 k bf16 =128B rows, SWZ128]   32KB
#define SM_W1L   32768      // W1T lo                                        32KB
#define SM_W2H   65536      // W2T hi [96 n][256 k bf16 =512B rows, SWZ512]  48KB
#define SM_W2L   114688     // W2T lo                                        48KB
#define SM_X     163840     // X dbuf: buf*8192 + (hi 0 / lo 4096), SWZ128   16KB
#define SM_HH    180224     // h hi [32 r][256 bf16 =512B rows, SWZ512]      16KB
#define SM_HL    196608     // h lo                                          16KB
#define SM_PP    180224     // spline params f32[32][96] (overlays h)
#define SM_B1    212992     // b1 f32[256]
#define SM_B2    214016     // b2 f32[96]
#define SM_TOTAL 214400

#define SWZ128(o) ((uint32_t)(o) ^ (((uint32_t)(o) >> 3) & 0x70u))
#define SWZ512(o) ((uint32_t)(o) ^ (((uint32_t)(o) >> 5) & 0x70u))

// ---------------- pre-split weights (device globals) ----------------
__device__ uint32_t g_W1T_hi[NH * NFEAT / 2];   // [n][kpair]
__device__ uint32_t g_W1T_lo[NH * NFEAT / 2];
__device__ uint32_t g_W2T_hi[NP * NH / 2];      // [n][kpair]
__device__ uint32_t g_W2T_lo[NP * NH / 2];

// ---------------- helpers ----------------
static __device__ __forceinline__ uint32_t smem_u32(const void* p) {
    uint32_t a;
    asm("{ .reg .u64 t; cvta.to.shared.u64 t, %1; cvt.u32.u64 %0, t; }" : "=r"(a) : "l"(p));
    return a;
}
static __device__ __forceinline__ void ldsm_x4(uint32_t addr, uint32_t r[4]) {
    asm volatile("ldmatrix.sync.aligned.m8n8.x4.shared.b16 {%0,%1,%2,%3}, [%4];"
                 : "=r"(r[0]), "=r"(r[1]), "=r"(r[2]), "=r"(r[3]) : "r"(addr));
}
static __device__ __forceinline__ void ldsm_x2(uint32_t addr, uint32_t r[2]) {
    asm volatile("ldmatrix.sync.aligned.m8n8.x2.shared.b16 {%0,%1}, [%2];"
                 : "=r"(r[0]), "=r"(r[1]) : "r"(addr));
}
static __device__ __forceinline__ void mma16816(float c[4], const uint32_t a[4], const uint32_t b[2]) {
    asm volatile("mma.sync.aligned.m16n8k16.row.col.f32.bf16.bf16.f32 "
                 "{%0,%1,%2,%3}, {%4,%5,%6,%7}, {%8,%9}, {%0,%1,%2,%3};"
                 : "+f"(c[0]), "+f"(c[1]), "+f"(c[2]), "+f"(c[3])
                 : "r"(a[0]), "r"(a[1]), "r"(a[2]), "r"(a[3]), "r"(b[0]), "r"(b[1]));
}
static __device__ __forceinline__ uint32_t pack_hi(float v0, float v1) {
    __nv_bfloat16 h0 = __float2bfloat16_rn(v0), h1 = __float2bfloat16_rn(v1);
    return (uint32_t)__bfloat16_as_ushort(h0) | ((uint32_t)__bfloat16_as_ushort(h1) << 16);
}
static __device__ __forceinline__ uint32_t pack_lo(float v0, float v1) {
    __nv_bfloat16 h0 = __float2bfloat16_rn(v0), h1 = __float2bfloat16_rn(v1);
    __nv_bfloat16 l0 = __float2bfloat16_rn(v0 - __bfloat162float(h0));
    __nv_bfloat16 l1 = __float2bfloat16_rn(v1 - __bfloat162float(h1));
    return (uint32_t)__bfloat16_as_ushort(l0) | ((uint32_t)__bfloat16_as_ushort(l1) << 16);
}
static __device__ __forceinline__ float softplus_f(float x) {
    return (x > 0.0f) ? (x + log1pf(expf(-x))) : log1pf(expf(x));
}

// ---------------- prep: split W1^T, W2^T into bf16 hi/lo [n][k] pairs ----------------
__global__ void prep_kernel(const float* __restrict__ W1, const float* __restrict__ W2)
{
    int i = blockIdx.x * blockDim.x + threadIdx.x;
    if (i < NH * NFEAT / 2) {                 // W1 [64][256] -> W1T[n][k]
        int n = i >> 5, kp = i & 31;
        float w0 = W1[(2 * kp)     * NH + n];
        float w1 = W1[(2 * kp + 1) * NH + n];
        g_W1T_hi[i] = pack_hi(w0, w1);
        g_W1T_lo[i] = pack_lo(w0, w1);
    }
    int j = i - NH * NFEAT / 2;
    if (j >= 0 && j < NP * NH / 2) {          // W2 [256][96] -> W2T[n][k]
        int n = j >> 7, kp = j & 127;
        float w0 = W2[(2 * kp)     * NP + n];
        float w1 = W2[(2 * kp + 1) * NP + n];
        g_W2T_hi[j] = pack_hi(w0, w1);
        g_W2T_lo[j] = pack_lo(w0, w1);
    }
}

// ---------------- persistent fused kernel ----------------
__global__ __launch_bounds__(NT, 1)
void cyl_pers_kernel(const float* __restrict__ theta,
                     const float* __restrict__ xc,
                     const float* __restrict__ b1,
                     const float* __restrict__ b2,
                     const float* __restrict__ eta,
                     float* __restrict__ out,
                     int B, int ntiles)
{
    extern __shared__ char smem[];
    const uint32_t smb = smem_u32(smem);
    const int t = threadIdx.x;
    const int w = t >> 5;
    const int l = t & 31;

    // ---- one-time weight + bias staging ----
    for (int i = t; i < NH * NFEAT / 2; i += NT) {        // W1T
        int n = i >> 5, kp = i & 31;
        uint32_t off = SWZ128(n * 128 + kp * 4);
        *(uint32_t*)(smem + SM_W1H + off) = g_W1T_hi[i];
        *(uint32_t*)(smem + SM_W1L + off) = g_W1T_lo[i];
    }
    for (int i = t; i < NP * NH / 2; i += NT) {           // W2T
        int n = i >> 7, kp = i & 127;
        uint32_t off = SWZ512(n * 512 + kp * 4);
        *(uint32_t*)(smem + SM_W2H + off) = g_W2T_hi[i];
        *(uint32_t*)(smem + SM_W2L + off) = g_W2T_lo[i];
    }
    ((float*)(smem + SM_B1))[t] = b1[t];
    if (t < NP) ((float*)(smem + SM_B2))[t] = b2[t];
    const float e0 = eta[0];

    // lane address components (byte offsets before swizzle)
    const int l4 = l & 15;
    const uint32_t a128 = (uint32_t)(l4 * 128 + ((l >> 4) & 1) * 16);
    const uint32_t b128 = (uint32_t)((l & 7) * 128 + ((l >> 3) & 1) * 16);
    const uint32_t a512 = (uint32_t)(l4 * 512 + ((l >> 4) & 1) * 16);
    const uint32_t b512 = (uint32_t)((l & 7) * 512 + ((l >> 3) & 1) * 16);
    const int rq = l >> 2, cq = 2 * (l & 3);
    const int mg = w >> 2, ng = w & 3;

    // X tile staging: per thread 4 float2 (row = idx>>5, kpair = idx&31)
    const float2* xp = (const float2*)xc;
    float2 xv[4];

    // preload first tile
    int tile = blockIdx.x;
    {
        #pragma unroll
        for (int j = 0; j < 4; j++) {
            int i = t + j * NT;
            int r = i >> 5, kp = i & 31;
            int row = tile * TM + r;
            xv[j] = (row < B) ? xp[row * 32 + kp] : make_float2(0.f, 0.f);
        }
        #pragma unroll
        for (int j = 0; j < 4; j++) {
            int i = t + j * NT;
            int r = i >> 5, kp = i & 31;
            uint32_t off = SWZ128(r * 128 + kp * 4);
            *(uint32_t*)(smem + SM_X + off)        = pack_hi(xv[j].x, xv[j].y);
            *(uint32_t*)(smem + SM_X + 4096 + off) = pack_lo(xv[j].x, xv[j].y);
        }
    }
    __syncthreads();

    int buf = 0;
    for (; tile < ntiles; tile += gridDim.x, buf ^= 1) {
        const int row0 = tile * TM;
        const int ntile = tile + gridDim.x;
        const bool have_next = ntile < ntiles;

        // prefetch next X into regs (latency hidden behind both MMAs)
        if (have_next) {
            #pragma unroll
            for (int j = 0; j < 4; j++) {
                int i = t + j * NT;
                int r = i >> 5, kp = i & 31;
                int row = ntile * TM + r;
                xv[j] = (row < B) ? xp[row * 32 + kp] : make_float2(0.f, 0.f);
            }
        }

        // ---- stage 1: C1 = X @ W1 (P = hh, Q = hl+lh) ----
        // warp w owns cols [32w, 32w+32): 4 n-tiles x 2 m-tiles
        float P1[2][4][4], Q1[2][4][4];
        #pragma unroll
        for (int m = 0; m < 2; m++)
            #pragma unroll
            for (int n = 0; n < 4; n++)
                #pragma unroll
                for (int q = 0; q < 4; q++) { P1[m][n][q] = 0.f; Q1[m][n][q] = 0.f; }

        const uint32_t xbase = smb + SM_X + (uint32_t)buf * 8192;
        #pragma unroll
        for (int k = 0; k < 4; k++) {
            uint32_t Ah[2][4], Al[2][4];
            #pragma unroll
            for (int m = 0; m < 2; m++) {
                uint32_t o = a128 + (uint32_t)(m * 2048 + k * 32);
                ldsm_x4(xbase +        SWZ128(o), Ah[m]);
                ldsm_x4(xbase + 4096 + SWZ128(o), Al[m]);
            }
            #pragma unroll
            for (int n = 0; n < 4; n++) {
                uint32_t Bh[2], Bl[2];
                uint32_t ob = b128 + (uint32_t)((w * 32 + n * 8) * 128 + k * 32);
                ldsm_x2(smb + SM_W1H + SWZ128(ob), Bh);
                ldsm_x2(smb + SM_W1L + SWZ128(ob), Bl);
                #pragma unroll
                for (int m = 0; m < 2; m++) {
                    mma16816(P1[m][n], Ah[m], Bh);
                    mma16816(Q1[m][n], Ah[m], Bl);
                    mma16816(Q1[m][n], Al[m], Bh);
                }
            }
        }

        // ---- epilogue 1: h = relu(C1 + b1) -> bf16 hi/lo smem (SWZ512) ----
        {
            const float* b1s = (const float*)(smem + SM_B1);
            #pragma unroll
            for (int n = 0; n < 4; n++) {
                int col = w * 32 + n * 8 + cq;
                float bb0 = b1s[col], bb1 = b1s[col + 1];
                #pragma unroll
                for (int m = 0; m < 2; m++) {
                    int r0 = m * 16 + rq;
                    float v0 = fmaxf(P1[m][n][0] + Q1[m][n][0] + bb0, 0.f);
                    float v1 = fmaxf(P1[m][n][1] + Q1[m][n][1] + bb1, 0.f);
                    float v2 = fmaxf(P1[m][n][2] + Q1[m][n][2] + bb0, 0.f);
                    float v3 = fmaxf(P1[m][n][3] + Q1[m][n][3] + bb1, 0.f);
                    uint32_t o0 = SWZ512(r0 * 512 + col * 2);
                    uint32_t o1 = SWZ512((r0 + 8) * 512 + col * 2);
                    *(uint32_t*)(smem + SM_HH + o0) = pack_hi(v0, v1);
                    *(uint32_t*)(smem + SM_HL + o0) = pack_lo(v0, v1);
                    *(uint32_t*)(smem + SM_HH + o1) = pack_hi(v2, v3);
                    *(uint32_t*)(smem + SM_HL + o1) = pack_lo(v2, v3);
                }
            }
        }
        __syncthreads();   // h visible

        // ---- stage 2: C2 = h @ W2 ----
        // warp (mg, ng): rows [mg*16,+16), cols [ng*24,+24): 3 n-tiles
        float P2[3][4], Q2[3][4];
        #pragma unroll
        for (int n = 0; n < 3; n++)
            #pragma unroll
            for (int q = 0; q < 4; q++) { P2[n][q] = 0.f; Q2[n][q] = 0.f; }

        #pragma unroll 4
        for (int k = 0; k < 16; k++) {
            uint32_t Ah[4], Al[4];
            uint32_t oa = a512 + (uint32_t)(mg * 8192 + k * 32);
            ldsm_x4(smb + SM_HH + SWZ512(oa), Ah);
            ldsm_x4(smb + SM_HL + SWZ512(oa), Al);
            #pragma unroll
            for (int n = 0; n < 3; n++) {
                uint32_t Bh[2], Bl[2];
                uint32_t ob = b512 + (uint32_t)((ng * 24 + n * 8) * 512 + k * 32);
                ldsm_x2(smb + SM_W2H + SWZ512(ob), Bh);
                ldsm_x2(smb + SM_W2L + SWZ512(ob), Bl);
                mma16816(P2[n], Ah, Bh);
                mma16816(Q2[n], Ah, Bl);
                mma16816(Q2[n], Al, Bh);
            }
        }
        __syncthreads();   // stage-2 h reads done; pp region (== h) writable

        // ---- epilogue 2: pp = (C2 + b2) * eta ----
        {
            float* pp = (float*)(smem + SM_PP);
            const float* b2s = (const float*)(smem + SM_B2);
            #pragma unroll
            for (int n = 0; n < 3; n++) {
                int col = ng * 24 + n * 8 + cq;
                float bb0 = b2s[col], bb1 = b2s[col + 1];
                int r0 = mg * 16 + rq;
                pp[r0 * NP + col]           = (P2[n][0] + Q2[n][0] + bb0) * e0;
                pp[r0 * NP + col + 1]       = (P2[n][1] + Q2[n][1] + bb1) * e0;
                pp[(r0 + 8) * NP + col]     = (P2[n][2] + Q2[n][2] + bb0) * e0;
                pp[(r0 + 8) * NP + col + 1] = (P2[n][3] + Q2[n][3] + bb1) * e0;
            }
        }

        // store next X tile into alternate buffer (LDG issued at loop top)
        if (have_next) {
            uint32_t nb = (uint32_t)(buf ^ 1) * 8192;
            #pragma unroll
            for (int j = 0; j < 4; j++) {
                int i = t + j * NT;
                int r = i >> 5, kp = i & 31;
                uint32_t off = SWZ128(r * 128 + kp * 4);
                *(uint32_t*)(smem + SM_X + nb + off)        = pack_hi(xv[j].x, xv[j].y);
                *(uint32_t*)(smem + SM_X + nb + 4096 + off) = pack_lo(xv[j].x, xv[j].y);
            }
        }
        __syncthreads();   // pp visible; X sts done

        // ---- stage 3: circular RQ spline, warp per row, lane = bin ----
        {
            const float* pp = (const float*)(smem + SM_PP);
            const unsigned FULL = 0xffffffffu;
            float th4[4];
            #pragma unroll
            for (int j = 0; j < 4; j++) {
                int row = row0 + w + 8 * j;
                th4[j] = (row < B) ? theta[row] : 0.f;
            }

            #pragma unroll
            for (int j = 0; j < 4; j++) {
                int rr = w + 8 * j;
                int row = row0 + rr;
                if (row >= B) continue;       // warp-uniform

                float th_in = th4[j];
                float uw = pp[rr * NP + l];
                float uh = pp[rr * NP + NB + l];
                float ud = pp[rr * NP + 2 * NB + l] + DERIV_OFF;

                float mw = uw, mh = uh;
                #pragma unroll
                for (int o = 16; o; o >>= 1) {
                    mw = fmaxf(mw, __shfl_xor_sync(FULL, mw, o));
                    mh = fmaxf(mh, __shfl_xor_sync(FULL, mh, o));
                }
                float ew = expf(uw - mw), eh = expf(uh - mh);
                float sw = ew, sh = eh;
                #pragma unroll
                for (int o = 16; o; o >>= 1) {
                    sw += __shfl_xor_sync(FULL, sw, o);
                    sh += __shfl_xor_sync(FULL, sh, o);
                }
                float szw = MIN_WH + SIZE_SCALE * (ew / sw);
                float szh = MIN_WH + SIZE_SCALE * (eh / sh);

                float cw = szw, chs = szh;
                #pragma unroll
                for (int o = 1; o < 32; o <<= 1) {
                    float a = __shfl_up_sync(FULL, cw,  o);
                    float b = __shfl_up_sync(FULL, chs, o);
                    if (l >= o) { cw += a; chs += b; }
                }

                float kw = (l == 31) ? TWO_PI_F : TWO_PI_F * cw;
                float kh = (l == 31) ? TWO_PI_F : TWO_PI_F * chs;

                unsigned bal = __ballot_sync(FULL, th_in >= kw);
                int bin = __popc(bal);
                if (bin > NB - 1) bin = NB - 1;
                int lo = (bin > 0) ? bin - 1 : 0;

                float cw_hi = __shfl_sync(FULL, kw, bin);
                float cw_lo = __shfl_sync(FULL, kw, lo);
                float ch_hi = __shfl_sync(FULL, kh, bin);
                float ch_lo = __shfl_sync(FULL, kh, lo);
                if (bin == 0) { cw_lo = 0.0f; ch_lo = 0.0f; }

                float in_w = cw_hi - cw_lo;
                float in_h = ch_hi - ch_lo;

                float dsp  = MIN_D + softplus_f(ud);
                float d_k  = __shfl_sync(FULL, dsp, bin);
                float d_k1 = __shfl_sync(FULL, dsp, (bin + 1) & 31);

                float delta = in_h / in_w;
                float th    = (th_in - cw_lo) / in_w;
                float om    = th * (1.0f - th);
                float den   = delta + (d_k1 + d_k - 2.0f * delta) * om;
                float num   = in_h * (delta * th * th + d_k * om);
                float outv  = ch_lo + num / den;

                float omt = 1.0f - th;
                float dn  = delta * delta * (d_k1 * th * th + 2.0f * delta * om + d_k * omt * omt);
                float lad = logf(dn) - 2.0f * logf(den);

                if (l == 0) {
                    out[row]     = outv;
                    out[B + row] = lad;
                }
            }
        }
        __syncthreads();   // spline pp reads done before next epi1 overwrites h/pp
    }
}

extern "C" void kernel_launch(void* const* d_in, const int* in_sizes, int n_in,
                              void* d_out, int out_size)
{
    const float* theta = (const float*)d_in[0];
    const float* xc    = (const float*)d_in[1];
    const float* W1    = (const float*)d_in[2];
    const float* b1    = (const float*)d_in[3];
    const float* W2    = (const float*)d_in[4];
    const float* b2    = (const float*)d_in[5];
    const float* eta   = (const float*)d_in[6];
    float* out = (float*)d_out;

    int B = in_sizes[0];

    static int nsm = 0;
    if (nsm == 0) {
        cudaDeviceProp prop;
        if (cudaGetDeviceProperties(&prop, 0) == cudaSuccess && prop.multiProcessorCount > 0)
            nsm = prop.multiProcessorCount;
        else
            nsm = 148;
        cudaFuncSetAttribute(cyl_pers_kernel, cudaFuncAttributeMaxDynamicSharedMemorySize, SM_TOTAL);
    }

    int prep_elems = NH * NFEAT / 2 + NP * NH / 2;
    prep_kernel<<<(prep_elems + 255) / 256, 256>>>(W1, W2);

    int ntiles = (B + TM - 1) / TM;
    int grid = nsm < ntiles ? nsm : ntiles;
    cyl_pers_kernel<<<grid, NT, SM_TOTAL>>>(theta, xc, b1, b2, eta, out, B, ntiles);
}

// round 9
// speedup vs baseline: 2.4349x; 1.2417x over previous
#include <cuda_runtime.h>
#include <cuda_bf16.h>
#include <math.h>
#include <stdint.h>

// ---------------- problem constants ----------------
#define NB     32
#define NFEAT  64
#define NH     256
#define NP     96
#define TM     32           // rows per tile
#define NT     512
#define PS     100          // padded row stride (floats) for pp/partials: 100 mod 32 = 4

#define TWO_PI_F   6.2831853071795864769f
#define MIN_WH     1e-3f
#define MIN_D      1e-3f
#define DERIV_OFF  0.5413248546129181f     // log(e-1)
#define SIZE_SCALE (1.0f - 1e-3f * 32.0f)

// ---- smem layout (bytes) ----
#define SM_W1H   0          // W1T hi [256 n][64 k bf16 =128B rows, SWZ128]   32KB
#define SM_W1L   32768
#define SM_W2H   65536      // W2T hi [96 n][256 k bf16 =512B rows, SWZ512]   48KB
#define SM_W2L   114688
#define SM_X     163840     // X dbuf: buf*8192 + (hi 0 / lo 4096), SWZ128    16KB
#define SM_HH    180224     // h hi [32 r][256 bf16 =512B rows, SWZ512]       16KB
#define SM_HL    196608
#define SM_PP    180224     // spline params f32[32][PS] (overlays h hi)
#define SM_PART  212992     // stage-2 k-split partials f32[32][PS]           12.8KB
#define SM_B1    225792     // b1 f32[256]
#define SM_B2    226816     // b2 f32[96]
#define SM_TOTAL 227200

#define SWZ128(o) ((uint32_t)(o) ^ (((uint32_t)(o) >> 3) & 0x70u))
#define SWZ512(o) ((uint32_t)(o) ^ (((uint32_t)(o) >> 5) & 0x70u))

// ---------------- pre-split weights (device globals) ----------------
__device__ uint32_t g_W1T_hi[NH * NFEAT / 2];   // [n][kpair]
__device__ uint32_t g_W1T_lo[NH * NFEAT / 2];
__device__ uint32_t g_W2T_hi[NP * NH / 2];      // [n][kpair]
__device__ uint32_t g_W2T_lo[NP * NH / 2];

// ---------------- helpers ----------------
static __device__ __forceinline__ uint32_t smem_u32(const void* p) {
    uint32_t a;
    asm("{ .reg .u64 t; cvta.to.shared.u64 t, %1; cvt.u32.u64 %0, t; }" : "=r"(a) : "l"(p));
    return a;
}
static __device__ __forceinline__ void ldsm_x4(uint32_t addr, uint32_t r[4]) {
    asm volatile("ldmatrix.sync.aligned.m8n8.x4.shared.b16 {%0,%1,%2,%3}, [%4];"
                 : "=r"(r[0]), "=r"(r[1]), "=r"(r[2]), "=r"(r[3]) : "r"(addr));
}
static __device__ __forceinline__ void ldsm_x2(uint32_t addr, uint32_t r[2]) {
    asm volatile("ldmatrix.sync.aligned.m8n8.x2.shared.b16 {%0,%1}, [%2];"
                 : "=r"(r[0]), "=r"(r[1]) : "r"(addr));
}
static __device__ __forceinline__ void mma16816(float c[4], const uint32_t a[4], const uint32_t b[2]) {
    asm volatile("mma.sync.aligned.m16n8k16.row.col.f32.bf16.bf16.f32 "
                 "{%0,%1,%2,%3}, {%4,%5,%6,%7}, {%8,%9}, {%0,%1,%2,%3};"
                 : "+f"(c[0]), "+f"(c[1]), "+f"(c[2]), "+f"(c[3])
                 : "r"(a[0]), "r"(a[1]), "r"(a[2]), "r"(a[3]), "r"(b[0]), "r"(b[1]));
}
static __device__ __forceinline__ uint32_t pack_hi(float v0, float v1) {
    __nv_bfloat16 h0 = __float2bfloat16_rn(v0), h1 = __float2bfloat16_rn(v1);
    return (uint32_t)__bfloat16_as_ushort(h0) | ((uint32_t)__bfloat16_as_ushort(h1) << 16);
}
static __device__ __forceinline__ uint32_t pack_lo(float v0, float v1) {
    __nv_bfloat16 h0 = __float2bfloat16_rn(v0), h1 = __float2bfloat16_rn(v1);
    __nv_bfloat16 l0 = __float2bfloat16_rn(v0 - __bfloat162float(h0));
    __nv_bfloat16 l1 = __float2bfloat16_rn(v1 - __bfloat162float(h1));
    return (uint32_t)__bfloat16_as_ushort(l0) | ((uint32_t)__bfloat16_as_ushort(l1) << 16);
}
static __device__ __forceinline__ float softplus_f(float x) {
    return (x > 0.0f) ? (x + log1pf(expf(-x))) : log1pf(expf(x));
}

// ---------------- prep: split W1^T, W2^T into bf16 hi/lo [n][k] pairs ----------------
__global__ void prep_kernel(const float* __restrict__ W1, const float* __restrict__ W2)
{
    int i = blockIdx.x * blockDim.x + threadIdx.x;
    if (i < NH * NFEAT / 2) {                 // W1 [64][256] -> W1T[n][k]
        int n = i >> 5, kp = i & 31;
        float w0 = W1[(2 * kp)     * NH + n];
        float w1 = W1[(2 * kp + 1) * NH + n];
        g_W1T_hi[i] = pack_hi(w0, w1);
        g_W1T_lo[i] = pack_lo(w0, w1);
    }
    int j = i - NH * NFEAT / 2;
    if (j >= 0 && j < NP * NH / 2) {          // W2 [256][96] -> W2T[n][k]
        int n = j >> 7, kp = j & 127;
        float w0 = W2[(2 * kp)     * NP + n];
        float w1 = W2[(2 * kp + 1) * NP + n];
        g_W2T_hi[j] = pack_hi(w0, w1);
        g_W2T_lo[j] = pack_lo(w0, w1);
    }
}

// ---------------- persistent fused kernel ----------------
__global__ __launch_bounds__(NT, 1)
void cyl_pers_kernel(const float* __restrict__ theta,
                     const float* __restrict__ xc,
                     const float* __restrict__ b1,
                     const float* __restrict__ b2,
                     const float* __restrict__ eta,
                     float* __restrict__ out,
                     int B, int ntiles)
{
    extern __shared__ char smem[];
    const uint32_t smb = smem_u32(smem);
    const int t = threadIdx.x;
    const int w = t >> 5;          // 0..15
    const int l = t & 31;

    // ---- one-time weight + bias staging ----
    for (int i = t; i < NH * NFEAT / 2; i += NT) {        // W1T
        int n = i >> 5, kp = i & 31;
        uint32_t off = SWZ128(n * 128 + kp * 4);
        *(uint32_t*)(smem + SM_W1H + off) = g_W1T_hi[i];
        *(uint32_t*)(smem + SM_W1L + off) = g_W1T_lo[i];
    }
    for (int i = t; i < NP * NH / 2; i += NT) {           // W2T
        int n = i >> 7, kp = i & 127;
        uint32_t off = SWZ512(n * 512 + kp * 4);
        *(uint32_t*)(smem + SM_W2H + off) = g_W2T_hi[i];
        *(uint32_t*)(smem + SM_W2L + off) = g_W2T_lo[i];
    }
    if (t < NH) ((float*)(smem + SM_B1))[t] = b1[t];
    if (t < NP) ((float*)(smem + SM_B2))[t] = b2[t];
    const float e0 = eta[0];

    // lane address components
    const int l4 = l & 15;
    const uint32_t a128 = (uint32_t)(l4 * 128 + ((l >> 4) & 1) * 16);
    const uint32_t b128 = (uint32_t)((l & 7) * 128 + ((l >> 3) & 1) * 16);
    const uint32_t a512 = (uint32_t)(l4 * 512 + ((l >> 4) & 1) * 16);
    const uint32_t b512 = (uint32_t)((l & 7) * 512 + ((l >> 3) & 1) * 16);
    const int rq = l >> 2, cq = 2 * (l & 3);

    // stage-1 mapping: 8 col-groups x 2 m-groups
    const int w8 = w & 7, mt = w >> 3;
    // stage-2 mapping: kslice x mg x ng
    const int ks = w >> 3, mg = (w >> 2) & 1, ng = w & 3;

    // X tile staging: 1024 float2 per tile -> 2 per thread
    const float2* xp = (const float2*)xc;
    float2 xv[2];

    // preload first tile
    int tile = blockIdx.x;
    {
        #pragma unroll
        for (int j = 0; j < 2; j++) {
            int i = t + j * NT;
            int r = i >> 5, kp = i & 31;
            int row = tile * TM + r;
            xv[j] = (row < B) ? xp[row * 32 + kp] : make_float2(0.f, 0.f);
        }
        #pragma unroll
        for (int j = 0; j < 2; j++) {
            int i = t + j * NT;
            int r = i >> 5, kp = i & 31;
            uint32_t off = SWZ128(r * 128 + kp * 4);
            *(uint32_t*)(smem + SM_X + off)        = pack_hi(xv[j].x, xv[j].y);
            *(uint32_t*)(smem + SM_X + 4096 + off) = pack_lo(xv[j].x, xv[j].y);
        }
    }
    __syncthreads();

    int buf = 0;
    for (; tile < ntiles; tile += gridDim.x, buf ^= 1) {
        const int row0 = tile * TM;
        const int ntile = tile + gridDim.x;
        const bool have_next = ntile < ntiles;

        // prefetch next X into regs
        if (have_next) {
            #pragma unroll
            for (int j = 0; j < 2; j++) {
                int i = t + j * NT;
                int r = i >> 5, kp = i & 31;
                int row = ntile * TM + r;
                xv[j] = (row < B) ? xp[row * 32 + kp] : make_float2(0.f, 0.f);
            }
        }

        // ---- stage 1: C1 = X @ W1 ; warp = m-tile mt (16 rows) x cols [32*w8,+32) ----
        float P1[4][4], Q1[4][4];
        #pragma unroll
        for (int n = 0; n < 4; n++)
            #pragma unroll
            for (int q = 0; q < 4; q++) { P1[n][q] = 0.f; Q1[n][q] = 0.f; }

        const uint32_t xbase = smb + SM_X + (uint32_t)buf * 8192;
        #pragma unroll
        for (int k = 0; k < 4; k++) {
            uint32_t Ah[4], Al[4];
            uint32_t o = a128 + (uint32_t)(mt * 2048 + k * 32);
            ldsm_x4(xbase +        SWZ128(o), Ah);
            ldsm_x4(xbase + 4096 + SWZ128(o), Al);
            #pragma unroll
            for (int n = 0; n < 4; n++) {
                uint32_t Bh[2], Bl[2];
                uint32_t ob = b128 + (uint32_t)((w8 * 32 + n * 8) * 128 + k * 32);
                ldsm_x2(smb + SM_W1H + SWZ128(ob), Bh);
                ldsm_x2(smb + SM_W1L + SWZ128(ob), Bl);
                mma16816(P1[n], Ah, Bh);
                mma16816(Q1[n], Ah, Bl);
                mma16816(Q1[n], Al, Bh);
            }
        }

        // ---- epilogue 1: h = relu(C1 + b1) -> bf16 hi/lo smem (SWZ512) ----
        {
            const float* b1s = (const float*)(smem + SM_B1);
            #pragma unroll
            for (int n = 0; n < 4; n++) {
                int col = w8 * 32 + n * 8 + cq;
                float bb0 = b1s[col], bb1 = b1s[col + 1];
                int r0 = mt * 16 + rq;
                float v0 = fmaxf(P1[n][0] + Q1[n][0] + bb0, 0.f);
                float v1 = fmaxf(P1[n][1] + Q1[n][1] + bb1, 0.f);
                float v2 = fmaxf(P1[n][2] + Q1[n][2] + bb0, 0.f);
                float v3 = fmaxf(P1[n][3] + Q1[n][3] + bb1, 0.f);
                uint32_t o0 = SWZ512(r0 * 512 + col * 2);
                uint32_t o1 = SWZ512((r0 + 8) * 512 + col * 2);
                *(uint32_t*)(smem + SM_HH + o0) = pack_hi(v0, v1);
                *(uint32_t*)(smem + SM_HL + o0) = pack_lo(v0, v1);
                *(uint32_t*)(smem + SM_HH + o1) = pack_hi(v2, v3);
                *(uint32_t*)(smem + SM_HL + o1) = pack_lo(v2, v3);
            }
        }
        __syncthreads();   // h visible

        // ---- stage 2: C2 = h @ W2 ; warp = kslice ks, rows [mg*16,+16), cols [ng*24,+24) ----
        float P2[3][4], Q2[3][4];
        #pragma unroll
        for (int n = 0; n < 3; n++)
            #pragma unroll
            for (int q = 0; q < 4; q++) { P2[n][q] = 0.f; Q2[n][q] = 0.f; }

        #pragma unroll
        for (int k = 0; k < 8; k++) {
            int kk = ks * 8 + k;
            uint32_t Ah[4], Al[4];
            uint32_t oa = a512 + (uint32_t)(mg * 8192 + kk * 32);
            ldsm_x4(smb + SM_HH + SWZ512(oa), Ah);
            ldsm_x4(smb + SM_HL + SWZ512(oa), Al);
            #pragma unroll
            for (int n = 0; n < 3; n++) {
                uint32_t Bh[2], Bl[2];
                uint32_t ob = b512 + (uint32_t)((ng * 24 + n * 8) * 512 + kk * 32);
                ldsm_x2(smb + SM_W2H + SWZ512(ob), Bh);
                ldsm_x2(smb + SM_W2L + SWZ512(ob), Bl);
                mma16816(P2[n], Ah, Bh);
                mma16816(Q2[n], Ah, Bl);
                mma16816(Q2[n], Al, Bh);
            }
        }

        // kslice-1 warps: write partials (padded stride PS -> conflict-free)
        if (ks == 1) {
            float* part = (float*)(smem + SM_PART);
            #pragma unroll
            for (int n = 0; n < 3; n++) {
                int col = ng * 24 + n * 8 + cq;
                int r0 = mg * 16 + rq;
                part[r0 * PS + col]           = P2[n][0] + Q2[n][0];
                part[r0 * PS + col + 1]       = P2[n][1] + Q2[n][1];
                part[(r0 + 8) * PS + col]     = P2[n][2] + Q2[n][2];
                part[(r0 + 8) * PS + col + 1] = P2[n][3] + Q2[n][3];
            }
        }
        __syncthreads();   // partials visible; all h reads done (pp region writable)

        // kslice-0 warps: reduce + epilogue 2
        if (ks == 0) {
            float* pp = (float*)(smem + SM_PP);
            const float* part = (const float*)(smem + SM_PART);
            const float* b2s = (const float*)(smem + SM_B2);
            #pragma unroll
            for (int n = 0; n < 3; n++) {
                int col = ng * 24 + n * 8 + cq;
                float bb0 = b2s[col], bb1 = b2s[col + 1];
                int r0 = mg * 16 + rq;
                pp[r0 * PS + col]           = (P2[n][0] + Q2[n][0] + part[r0 * PS + col]           + bb0) * e0;
                pp[r0 * PS + col + 1]       = (P2[n][1] + Q2[n][1] + part[r0 * PS + col + 1]       + bb1) * e0;
                pp[(r0 + 8) * PS + col]     = (P2[n][2] + Q2[n][2] + part[(r0 + 8) * PS + col]     + bb0) * e0;
                pp[(r0 + 8) * PS + col + 1] = (P2[n][3] + Q2[n][3] + part[(r0 + 8) * PS + col + 1] + bb1) * e0;
            }
        }

        // store next X tile into alternate buffer
        if (have_next) {
            uint32_t nb = (uint32_t)(buf ^ 1) * 8192;
            #pragma unroll
            for (int j = 0; j < 2; j++) {
                int i = t + j * NT;
                int r = i >> 5, kp = i & 31;
                uint32_t off = SWZ128(r * 128 + kp * 4);
                *(uint32_t*)(smem + SM_X + nb + off)        = pack_hi(xv[j].x, xv[j].y);
                *(uint32_t*)(smem + SM_X + nb + 4096 + off) = pack_lo(xv[j].x, xv[j].y);
            }
        }
        __syncthreads();   // pp visible; X sts done

        // ---- stage 3: circular RQ spline, warp per row (16 warps x 2 rows) ----
        {
            const float* pp = (const float*)(smem + SM_PP);
            const unsigned FULL = 0xffffffffu;
            float th2[2];
            #pragma unroll
            for (int j = 0; j < 2; j++) {
                int row = row0 + w + 16 * j;
                th2[j] = (row < B) ? theta[row] : 0.f;
            }

            #pragma unroll
            for (int j = 0; j < 2; j++) {
                int rr = w + 16 * j;
                int row = row0 + rr;
                if (row >= B) continue;       // warp-uniform

                float th_in = th2[j];
                float uw = pp[rr * PS + l];
                float uh = pp[rr * PS + NB + l];
                float ud = pp[rr * PS + 2 * NB + l] + DERIV_OFF;

                float mw = uw, mh = uh;
                #pragma unroll
                for (int o = 16; o; o >>= 1) {
                    mw = fmaxf(mw, __shfl_xor_sync(FULL, mw, o));
                    mh = fmaxf(mh, __shfl_xor_sync(FULL, mh, o));
                }
                float ew = expf(uw - mw), eh = expf(uh - mh);
                float sw = ew, sh = eh;
                #pragma unroll
                for (int o = 16; o; o >>= 1) {
                    sw += __shfl_xor_sync(FULL, sw, o);
                    sh += __shfl_xor_sync(FULL, sh, o);
                }
                float szw = MIN_WH + SIZE_SCALE * (ew / sw);
                float szh = MIN_WH + SIZE_SCALE * (eh / sh);

                float cw = szw, chs = szh;
                #pragma unroll
                for (int o = 1; o < 32; o <<= 1) {
                    float a = __shfl_up_sync(FULL, cw,  o);
                    float b = __shfl_up_sync(FULL, chs, o);
                    if (l >= o) { cw += a; chs += b; }
                }

                float kw = (l == 31) ? TWO_PI_F : TWO_PI_F * cw;
                float kh = (l == 31) ? TWO_PI_F : TWO_PI_F * chs;

                unsigned bal = __ballot_sync(FULL, th_in >= kw);
                int bin = __popc(bal);
                if (bin > NB - 1) bin = NB - 1;
                int lo = (bin > 0) ? bin - 1 : 0;

                float cw_hi = __shfl_sync(FULL, kw, bin);
                float cw_lo = __shfl_sync(FULL, kw, lo);
                float ch_hi = __shfl_sync(FULL, kh, bin);
                float ch_lo = __shfl_sync(FULL, kh, lo);
                if (bin == 0) { cw_lo = 0.0f; ch_lo = 0.0f; }

                float in_w = cw_hi - cw_lo;
                float in_h = ch_hi - ch_lo;

                float dsp  = MIN_D + softplus_f(ud);
                float d_k  = __shfl_sync(FULL, dsp, bin);
                float d_k1 = __shfl_sync(FULL, dsp, (bin + 1) & 31);

                float delta = in_h / in_w;
                float th    = (th_in - cw_lo) / in_w;
                float om    = th * (1.0f - th);
                float den   = delta + (d_k1 + d_k - 2.0f * delta) * om;
                float num   = in_h * (delta * th * th + d_k * om);
                float outv  = ch_lo + num / den;

                float omt = 1.0f - th;
                float dn  = delta * delta * (d_k1 * th * th + 2.0f * delta * om + d_k * omt * omt);
                float lad = logf(dn) - 2.0f * logf(den);

                if (l == 0) {
                    out[row]     = outv;
                    out[B + row] = lad;
                }
            }
        }
        __syncthreads();   // spline pp reads done before next epi1 overwrites h/pp
    }
}

extern "C" void kernel_launch(void* const* d_in, const int* in_sizes, int n_in,
                              void* d_out, int out_size)
{
    const float* theta = (const float*)d_in[0];
    const float* xc    = (const float*)d_in[1];
    const float* W1    = (const float*)d_in[2];
    const float* b1    = (const float*)d_in[3];
    const float* W2    = (const float*)d_in[4];
    const float* b2    = (const float*)d_in[5];
    const float* eta   = (const float*)d_in[6];
    float* out = (float*)d_out;

    int B = in_sizes[0];

    static int nsm = 0;
    if (nsm == 0) {
        cudaDeviceProp prop;
        if (cudaGetDeviceProperties(&prop, 0) == cudaSuccess && prop.multiProcessorCount > 0)
            nsm = prop.multiProcessorCount;
        else
            nsm = 148;
        cudaFuncSetAttribute(cyl_pers_kernel, cudaFuncAttributeMaxDynamicSharedMemorySize, SM_TOTAL);
    }

    int prep_elems = NH * NFEAT / 2 + NP * NH / 2;
    prep_kernel<<<(prep_elems + 255) / 256, 256>>>(W1, W2);

    int ntiles = (B + TM - 1) / TM;
    int grid = nsm < ntiles ? nsm : ntiles;
    cyl_pers_kernel<<<grid, NT, SM_TOTAL>>>(theta, xc, b1, b2, eta, out, B, ntiles);
}